// round 2
// baseline (speedup 1.0000x reference)
#include <cuda_runtime.h>

// FullAttention: causal, B*H = 32, S = 2048, D = 64, fp32.
// Layout: q/k/v/out all [BH, S, D] contiguous.

#define S_LEN 2048
#define HEAD_D 64
#define D4 (HEAD_D / 4)      // 16 float4 per row
#define ROWS 128             // q rows per block (1 thread = 1 q row)
#define TK 64                // kv rows per shared tile
#define NBH 32
#define SM_SCALE 0.125f      // 1/sqrt(64)

__device__ __forceinline__ float dot4(float4 a, float4 b, float acc) {
    acc = fmaf(a.x, b.x, acc);
    acc = fmaf(a.y, b.y, acc);
    acc = fmaf(a.z, b.z, acc);
    acc = fmaf(a.w, b.w, acc);
    return acc;
}

__global__ __launch_bounds__(ROWS, 2)
void fa_causal_kernel(const float* __restrict__ q,
                      const float* __restrict__ k,
                      const float* __restrict__ v,
                      float* __restrict__ out) {
    __shared__ float4 sK[TK * D4];
    __shared__ float4 sV[TK * D4];

    const int bh  = blockIdx.y;
    // Heaviest q-tiles (largest causal extent) launch first for better wave balance.
    const int qbase = (gridDim.x - 1 - blockIdx.x) * ROWS;
    const int tid = threadIdx.x;
    const int r   = qbase + tid;           // this thread's query row

    const float4* qrow = (const float4*)(q + ((long)bh * S_LEN + r) * HEAD_D);
    const float4* kbh  = (const float4*)(k + (long)bh * S_LEN * HEAD_D);
    const float4* vbh  = (const float4*)(v + (long)bh * S_LEN * HEAD_D);

    // Query row + output accumulator in registers.
    float4 qr[D4];
    float4 o[D4];
#pragma unroll
    for (int i = 0; i < D4; ++i) {
        qr[i] = qrow[i];
        o[i]  = make_float4(0.f, 0.f, 0.f, 0.f);
    }
    float m = -1e30f;
    float l = 0.f;

    const int n_tiles = (qbase + ROWS + TK - 1) / TK;

    for (int t = 0; t < n_tiles; ++t) {
        const int kv0 = t * TK;

        __syncthreads();   // protect previous tile's consumers
        // Cooperative load: TK*D4 = 1024 float4 per array, 128 threads -> 8 each.
#pragma unroll
        for (int i = 0; i < (TK * D4) / ROWS; ++i) {
            const int idx = i * ROWS + tid;
            sK[idx] = kbh[kv0 * D4 + idx];
            sV[idx] = vbh[kv0 * D4 + idx];
        }
        __syncthreads();

        // Full tiles (kv0 + TK - 1 <= qbase) need no causal check.
        const bool masked = (kv0 + TK - 1 > qbase);
        const int jmax = masked ? min(TK, r - kv0 + 1) : TK;  // may be <= 0 -> skip

        for (int j = 0; j < jmax; ++j) {
            // s = <q_r, k_j> * scale ; 4 independent FMA chains for ILP.
            float s0 = 0.f, s1 = 0.f, s2 = 0.f, s3 = 0.f;
#pragma unroll
            for (int d = 0; d < D4; d += 4) {
                s0 = dot4(qr[d + 0], sK[j * D4 + d + 0], s0);
                s1 = dot4(qr[d + 1], sK[j * D4 + d + 1], s1);
                s2 = dot4(qr[d + 2], sK[j * D4 + d + 2], s2);
                s3 = dot4(qr[d + 3], sK[j * D4 + d + 3], s3);
            }
            const float s = ((s0 + s1) + (s2 + s3)) * SM_SCALE;

            float p;
            if (s > m) {
                // Max moved: rescale accumulator (rare after warm-up).
                const float corr = __expf(m - s);
                m = s;
                l *= corr;
#pragma unroll
                for (int i = 0; i < D4; ++i) {
                    o[i].x *= corr; o[i].y *= corr;
                    o[i].z *= corr; o[i].w *= corr;
                }
                p = 1.0f;
            } else {
                p = __expf(s - m);
            }
            l += p;
#pragma unroll
            for (int i = 0; i < D4; ++i) {
                const float4 vv = sV[j * D4 + i];
                o[i].x = fmaf(p, vv.x, o[i].x);
                o[i].y = fmaf(p, vv.y, o[i].y);
                o[i].z = fmaf(p, vv.z, o[i].z);
                o[i].w = fmaf(p, vv.w, o[i].w);
            }
        }
    }

    const float inv = 1.0f / l;
    float4* orow = (float4*)(out + ((long)bh * S_LEN + r) * HEAD_D);
#pragma unroll
    for (int i = 0; i < D4; ++i) {
        orow[i] = make_float4(o[i].x * inv, o[i].y * inv,
                              o[i].z * inv, o[i].w * inv);
    }
}

extern "C" void kernel_launch(void* const* d_in, const int* in_sizes, int n_in,
                              void* d_out, int out_size) {
    (void)in_sizes; (void)n_in; (void)out_size;
    const float* q = (const float*)d_in[0];
    const float* k = (const float*)d_in[1];
    const float* v = (const float*)d_in[2];
    float* out = (float*)d_out;

    dim3 grid(S_LEN / ROWS, NBH);   // (16, 32)
    dim3 block(ROWS);               // 128 threads, 1 q row each
    fa_causal_kernel<<<grid, block>>>(q, k, v, out);
}